// round 2
// baseline (speedup 1.0000x reference)
#include <cuda_runtime.h>
#include <cuda_bf16.h>

#define QN 64
#define AN 32
#define BN 256
#define SN 2048

// Scratch (__device__ globals; no allocation allowed).
// Interleaved bf16 layout for a 64x64 matrix W: element (i,j) at
//   bf16 index  (i>>3)*512 + j*8 + (i&7)
// -> one 16B granule = rows i=c*8..c*8+7 of column j (chunk c).
__device__ __align__(16) static __nv_bfloat16 g_pairs[1024 * 4096];   // 8 MB: P[a0*32+a1]
__device__ __align__(16) static __nv_bfloat16 g_singles[32 * 4096];   // 256 KB: W[a]
__device__ __align__(16) static float g_Wf[32 * 4096];                // f32 W[a][i][j]

// ---------------------------------------------------------------------------
// Kernel 1: W[a][i][j] = softmax_j(T_logits[i][a][:]). One warp per (i,a).
// ---------------------------------------------------------------------------
__global__ void k_softmax(const float* __restrict__ T) {
    int warp = (blockIdx.x << 2) + (threadIdx.x >> 5);   // warp = i*32 + a
    int lane = threadIdx.x & 31;
    int i = warp >> 5, a = warp & 31;
    const float* row = T + warp * 64;                    // T[(i*32+a)*64 + j]
    float v0 = row[lane], v1 = row[lane + 32];
    float m = fmaxf(v0, v1);
#pragma unroll
    for (int o = 16; o; o >>= 1) m = fmaxf(m, __shfl_xor_sync(0xFFFFFFFFu, m, o));
    float e0 = expf(v0 - m), e1 = expf(v1 - m);
    float s = e0 + e1;
#pragma unroll
    for (int o = 16; o; o >>= 1) s += __shfl_xor_sync(0xFFFFFFFFu, s, o);
    float inv = 1.0f / s;
    float w0 = e0 * inv, w1 = e1 * inv;

    float* wf = g_Wf + a * 4096 + i * 64;
    wf[lane] = w0;
    wf[lane + 32] = w1;

    __nv_bfloat16* sg = g_singles + a * 4096;
    int c = i >> 3, r = i & 7;
    sg[c * 512 + lane * 8 + r]        = __float2bfloat16(w0);
    sg[c * 512 + (lane + 32) * 8 + r] = __float2bfloat16(w1);
}

// ---------------------------------------------------------------------------
// Kernel 2: P[a0*32+a1] = W[a0] @ W[a1], f32 math, bf16 interleaved output.
// 1024 CTAs x 64 threads, 8x8 register tiles.
// ---------------------------------------------------------------------------
__global__ void k_pairs() {
    __shared__ __align__(16) float As[64][68];   // As[k][i] = A[i][k]
    __shared__ __align__(16) float Bs[64][64];   // Bs[k][j] = B[k][j]
    int a0 = blockIdx.x >> 5, a1 = blockIdx.x & 31;
    const float* A  = g_Wf + a0 * 4096;
    const float* Bm = g_Wf + a1 * 4096;
    int t = threadIdx.x;
    for (int idx = t; idx < 4096; idx += 64) {
        As[idx & 63][idx >> 6] = A[idx];
        Bs[idx >> 6][idx & 63] = Bm[idx];
    }
    __syncthreads();

    int j0 = (t & 7) << 3, i0 = (t >> 3) << 3;
    float acc[8][8];
#pragma unroll
    for (int ii = 0; ii < 8; ii++)
#pragma unroll
        for (int jj = 0; jj < 8; jj++) acc[ii][jj] = 0.f;

    for (int k = 0; k < 64; k++) {
        float av[8], bv[8];
        *(float4*)(av)     = *(const float4*)&As[k][i0];
        *(float4*)(av + 4) = *(const float4*)&As[k][i0 + 4];
        *(float4*)(bv)     = *(const float4*)&Bs[k][j0];
        *(float4*)(bv + 4) = *(const float4*)&Bs[k][j0 + 4];
#pragma unroll
        for (int ii = 0; ii < 8; ii++)
#pragma unroll
            for (int jj = 0; jj < 8; jj++)
                acc[ii][jj] = fmaf(av[ii], bv[jj], acc[ii][jj]);
    }

    // store interleaved: this thread covers chunk c = t>>3 (rows i0..i0+7), cols j0..j0+7
    __nv_bfloat16* dst = g_pairs + blockIdx.x * 4096 + (t >> 3) * 512;
#pragma unroll
    for (int jj = 0; jj < 8; jj++) {
        int j = j0 + jj;
        __nv_bfloat162 h0 = __floats2bfloat162_rn(acc[0][jj], acc[1][jj]);
        __nv_bfloat162 h1 = __floats2bfloat162_rn(acc[2][jj], acc[3][jj]);
        __nv_bfloat162 h2 = __floats2bfloat162_rn(acc[4][jj], acc[5][jj]);
        __nv_bfloat162 h3 = __floats2bfloat162_rn(acc[6][jj], acc[7][jj]);
        uint4 u;
        u.x = *(unsigned*)&h0; u.y = *(unsigned*)&h1;
        u.z = *(unsigned*)&h2; u.w = *(unsigned*)&h3;
        *(uint4*)(dst + j * 8) = u;
    }
}

// ---------------------------------------------------------------------------
// Kernel 3: forward recursion. One CTA (64 threads) per batch element.
// ---------------------------------------------------------------------------
__device__ __forceinline__ const uint4* mat_base(int m) {
    const __nv_bfloat16* g = (m & 1) ? g_singles : g_pairs;
    return (const uint4*)(g + (m & ~1));
}

#define LOADW(W, T_)                                                          \
    {                                                                         \
        const uint4* nb_ = mat_base(midx[(T_)]);                              \
        _Pragma("unroll")                                                     \
        for (int c_ = 0; c_ < 8; c_++) (W)[c_] = __ldg(nb_ + c_ * 64 + tid);  \
    }

#define STEP(W)                                                               \
    {                                                                         \
        const float* pc_ = psm[t & 1];                                        \
        float* pn_ = psm[(t + 1) & 1];                                        \
        float a0_ = 0.f, a1_ = 0.f, a2_ = 0.f, a3_ = 0.f;                     \
        _Pragma("unroll")                                                     \
        for (int c_ = 0; c_ < 8; c_++) {                                      \
            float4 pa_ = *(const float4*)(pc_ + c_ * 8);                      \
            float4 pb_ = *(const float4*)(pc_ + c_ * 8 + 4);                  \
            uint4 u_ = (W)[c_];                                               \
            a0_ = fmaf(__uint_as_float(u_.x << 16),         pa_.x, a0_);      \
            a1_ = fmaf(__uint_as_float(u_.x & 0xFFFF0000u), pa_.y, a1_);      \
            a2_ = fmaf(__uint_as_float(u_.y << 16),         pa_.z, a2_);      \
            a3_ = fmaf(__uint_as_float(u_.y & 0xFFFF0000u), pa_.w, a3_);      \
            a0_ = fmaf(__uint_as_float(u_.z << 16),         pb_.x, a0_);      \
            a1_ = fmaf(__uint_as_float(u_.z & 0xFFFF0000u), pb_.y, a1_);      \
            a2_ = fmaf(__uint_as_float(u_.w << 16),         pb_.z, a2_);      \
            a3_ = fmaf(__uint_as_float(u_.w & 0xFFFF0000u), pb_.w, a3_);      \
        }                                                                     \
        if (t + 2 < nsteps) LOADW(W, t + 2);                                  \
        pn_[tid] = (a0_ + a1_) + (a2_ + a3_);                                 \
        __syncthreads();                                                      \
        t++;                                                                  \
    }

__global__ void __launch_bounds__(64, 4)
k_forward(const int* __restrict__ x, const int* __restrict__ lengths,
          const float* __restrict__ f_logits, float* __restrict__ out) {
    __shared__ __align__(16) float psm[2][QN];
    __shared__ int midx[SN / 2];
    __shared__ float rsm[2][4];

    int b = blockIdx.x, tid = threadIdx.x;
    int L = lengths[b];
    int npairs = L >> 1, nsteps = (L + 1) >> 1;
    const int* xb = x + b * SN;

    // precompute matrix offsets (element offset into table; low bit = singles flag)
    for (int t2 = tid; t2 < nsteps; t2 += 64) {
        int off;
        if (t2 < npairs) off = (__ldg(xb + 2 * t2) * 32 + __ldg(xb + 2 * t2 + 1)) * 4096;
        else             off = __ldg(xb + 2 * t2) * 4096 | 1;
        midx[t2] = off;
    }
    psm[0][tid] = (tid == 0) ? 1.0f : 0.0f;
    __syncthreads();

    uint4 w0[8], w1[8];
    if (nsteps > 0) LOADW(w0, 0);
    if (nsteps > 1) LOADW(w1, 1);

    int t = 0;
    while (t < nsteps) {
        STEP(w0);
        if (t >= nsteps) break;
        STEP(w1);
    }

    // out[b] = log(sum p_j * softmax(f)_j) corrected by total mass:
    //        = log(S1) - log(S2) - log(Sp)   (invariant to any scaling of p)
    int wid = tid >> 5, lane = tid & 31;
    float fl = f_logits[tid];
    float M = fl;
#pragma unroll
    for (int o = 16; o; o >>= 1) M = fmaxf(M, __shfl_xor_sync(0xFFFFFFFFu, M, o));
    if (lane == 0) rsm[wid][3] = M;
    __syncthreads();
    M = fmaxf(rsm[0][3], rsm[1][3]);

    float e = expf(fl - M);
    float pj = psm[nsteps & 1][tid];
    float s1 = pj * e, s2 = e, sp = pj;
#pragma unroll
    for (int o = 16; o; o >>= 1) {
        s1 += __shfl_xor_sync(0xFFFFFFFFu, s1, o);
        s2 += __shfl_xor_sync(0xFFFFFFFFu, s2, o);
        sp += __shfl_xor_sync(0xFFFFFFFFu, sp, o);
    }
    if (lane == 0) { rsm[wid][0] = s1; rsm[wid][1] = s2; rsm[wid][2] = sp; }
    __syncthreads();
    if (tid == 0) {
        out[b] = logf(rsm[0][0] + rsm[1][0]) - logf(rsm[0][1] + rsm[1][1])
               - logf(rsm[0][2] + rsm[1][2]);
    }
}

extern "C" void kernel_launch(void* const* d_in, const int* in_sizes, int n_in,
                              void* d_out, int out_size) {
    const int*   x        = (const int*)d_in[0];       // [256, 2048]
    const int*   lengths  = (const int*)d_in[1];       // [256]
    const float* T_logits = (const float*)d_in[2];     // [64, 32, 64]
    const float* f_logits = (const float*)d_in[3];     // [64]
    float* out = (float*)d_out;                        // [256]

    k_softmax<<<512, 128>>>(T_logits);
    k_pairs<<<1024, 64>>>();
    k_forward<<<BN, 64>>>(x, lengths, f_logits, out);
}

// round 3
// speedup vs baseline: 1.3547x; 1.3547x over previous
#include <cuda_runtime.h>
#include <cuda_bf16.h>

#define QN 64
#define AN 32
#define BN 256
#define SN 2048

// Interleaved bf16 layout for a 64x64 matrix W: element (i,j) at
//   bf16 index  (i>>3)*512 + j*8 + (i&7)
// One 16B granule = rows 8c..8c+7 of column j. Column-j access = 8 x uint4,
// perfectly coalesced across a warp.
__device__ __align__(16) static __nv_bfloat16 g_pairs  [1024 * 4096];  // P[a0*32+a1]
__device__ __align__(16) static __nv_bfloat16 g_pairsT [1024 * 4096];  // P^T
__device__ __align__(16) static __nv_bfloat16 g_singles [32 * 4096];   // W[a]
__device__ __align__(16) static __nv_bfloat16 g_singlesT[32 * 4096];   // W[a]^T
__device__ __align__(16) static float g_Wf[32 * 4096];                 // f32 W[a]

// ---------------------------------------------------------------------------
// Kernel 1: W[a][i][j] = softmax_j(T_logits[i][a][:]). One warp per (i,a).
// Writes f32 W, bf16 interleaved W, and bf16 interleaved W^T.
// ---------------------------------------------------------------------------
__global__ void k_softmax(const float* __restrict__ T) {
    int warp = (blockIdx.x << 2) + (threadIdx.x >> 5);   // warp = i*32 + a
    int lane = threadIdx.x & 31;
    int i = warp >> 5, a = warp & 31;
    const float* row = T + warp * 64;
    float v0 = row[lane], v1 = row[lane + 32];
    float m = fmaxf(v0, v1);
#pragma unroll
    for (int o = 16; o; o >>= 1) m = fmaxf(m, __shfl_xor_sync(0xFFFFFFFFu, m, o));
    float e0 = expf(v0 - m), e1 = expf(v1 - m);
    float s = e0 + e1;
#pragma unroll
    for (int o = 16; o; o >>= 1) s += __shfl_xor_sync(0xFFFFFFFFu, s, o);
    float inv = 1.0f / s;
    float w0 = e0 * inv, w1 = e1 * inv;

    float* wf = g_Wf + a * 4096 + i * 64;
    wf[lane] = w0;
    wf[lane + 32] = w1;

    __nv_bfloat16* sg  = g_singles  + a * 4096;
    __nv_bfloat16* sgT = g_singlesT + a * 4096;
    int c = i >> 3, r = i & 7;
    int j0 = lane, j1 = lane + 32;
    sg[c * 512 + j0 * 8 + r] = __float2bfloat16(w0);
    sg[c * 512 + j1 * 8 + r] = __float2bfloat16(w1);
    // transposed: element (j,i) at ((j>>3)*512 + i*8 + (j&7))
    sgT[(j0 >> 3) * 512 + i * 8 + (j0 & 7)] = __float2bfloat16(w0);
    sgT[(j1 >> 3) * 512 + i * 8 + (j1 & 7)] = __float2bfloat16(w1);
}

// ---------------------------------------------------------------------------
// Kernel 2: P = W[a0] @ W[a1], f32 math; bf16 interleaved P and P^T outputs.
// 1024 CTAs x 64 threads, 8x8 register tiles.
// ---------------------------------------------------------------------------
__global__ void k_pairs() {
    __shared__ __align__(16) float As[64][68];   // As[k][i] = A[i][k]
    __shared__ __align__(16) float Bs[64][64];   // Bs[k][j] = B[k][j]
    int a0 = blockIdx.x >> 5, a1 = blockIdx.x & 31;
    const float* A  = g_Wf + a0 * 4096;
    const float* Bm = g_Wf + a1 * 4096;
    int t = threadIdx.x;
    for (int idx = t; idx < 4096; idx += 64) {
        As[idx & 63][idx >> 6] = A[idx];
        Bs[idx >> 6][idx & 63] = Bm[idx];
    }
    __syncthreads();

    int j0 = (t & 7) << 3, i0 = (t >> 3) << 3;
    float acc[8][8];
#pragma unroll
    for (int ii = 0; ii < 8; ii++)
#pragma unroll
        for (int jj = 0; jj < 8; jj++) acc[ii][jj] = 0.f;

    for (int k = 0; k < 64; k++) {
        float av[8], bv[8];
        *(float4*)(av)     = *(const float4*)&As[k][i0];
        *(float4*)(av + 4) = *(const float4*)&As[k][i0 + 4];
        *(float4*)(bv)     = *(const float4*)&Bs[k][j0];
        *(float4*)(bv + 4) = *(const float4*)&Bs[k][j0 + 4];
#pragma unroll
        for (int ii = 0; ii < 8; ii++)
#pragma unroll
            for (int jj = 0; jj < 8; jj++)
                acc[ii][jj] = fmaf(av[ii], bv[jj], acc[ii][jj]);
    }

    // normal: block rows i0..i0+7 (chunk i0>>3), cols j0..j0+7
    __nv_bfloat16* dst = g_pairs + blockIdx.x * 4096 + (i0 >> 3) * 512;
#pragma unroll
    for (int jj = 0; jj < 8; jj++) {
        __nv_bfloat162 h0 = __floats2bfloat162_rn(acc[0][jj], acc[1][jj]);
        __nv_bfloat162 h1 = __floats2bfloat162_rn(acc[2][jj], acc[3][jj]);
        __nv_bfloat162 h2 = __floats2bfloat162_rn(acc[4][jj], acc[5][jj]);
        __nv_bfloat162 h3 = __floats2bfloat162_rn(acc[6][jj], acc[7][jj]);
        uint4 u;
        u.x = *(unsigned*)&h0; u.y = *(unsigned*)&h1;
        u.z = *(unsigned*)&h2; u.w = *(unsigned*)&h3;
        *(uint4*)(dst + (j0 + jj) * 8) = u;
    }
    // transposed: P^T block rows j0..j0+7 (chunk j0>>3), cols i0..i0+7
    __nv_bfloat16* dstT = g_pairsT + blockIdx.x * 4096 + (j0 >> 3) * 512;
#pragma unroll
    for (int ii = 0; ii < 8; ii++) {
        __nv_bfloat162 h0 = __floats2bfloat162_rn(acc[ii][0], acc[ii][1]);
        __nv_bfloat162 h1 = __floats2bfloat162_rn(acc[ii][2], acc[ii][3]);
        __nv_bfloat162 h2 = __floats2bfloat162_rn(acc[ii][4], acc[ii][5]);
        __nv_bfloat162 h3 = __floats2bfloat162_rn(acc[ii][6], acc[ii][7]);
        uint4 u;
        u.x = *(unsigned*)&h0; u.y = *(unsigned*)&h1;
        u.z = *(unsigned*)&h2; u.w = *(unsigned*)&h3;
        *(uint4*)(dstT + (i0 + ii) * 8) = u;
    }
}

// ---------------------------------------------------------------------------
// Kernel 3: bidirectional forward recursion. One CTA (128 thr) per sequence.
// warps 0-1: left  alpha <- alpha * P   (64 threads, one column each)
// warps 2-3: right r     <- P * r       (64 threads, one row each, via P^T)
// ---------------------------------------------------------------------------

// packed f32x2 FMA: acc(2xf32 in u64) += unpack_bf16x2(u) * (pl, ph)
__device__ __forceinline__ void ffma2(unsigned long long& acc, unsigned u,
                                      float pl, float ph) {
    asm("{\n\t"
        ".reg .b32 wl, wh;\n\t"
        ".reg .b64 w2, p2;\n\t"
        "shl.b32 wl, %1, 16;\n\t"
        "and.b32 wh, %1, 0xFFFF0000;\n\t"
        "mov.b64 w2, {wl, wh};\n\t"
        "mov.b64 p2, {%2, %3};\n\t"
        "fma.rn.f32x2 %0, w2, p2, %0;\n\t"
        "}" : "+l"(acc) : "r"(u), "f"(pl), "f"(ph));
}
__device__ __forceinline__ void unpack2(unsigned long long a, float& lo, float& hi) {
    asm("mov.b64 {%0, %1}, %2;" : "=f"(lo), "=f"(hi) : "l"(a));
}

#define LOADW(W, T_)                                                           \
    {                                                                          \
        int off_ = midx[(T_)];                                                 \
        const uint4* base_ =                                                   \
            ((off_ & 1) ? singles : pairs) + ((off_ & ~1) >> 3) + j;           \
        _Pragma("unroll")                                                      \
        for (int c_ = 0; c_ < 8; c_++) (W)[c_] = __ldg(base_ + c_ * 64);       \
    }

#define STEPD(W)                                                               \
    {                                                                          \
        const float4* pc_ = (const float4*)psm[t & 1];                         \
        unsigned long long A_ = 0ull, B_ = 0ull;                               \
        _Pragma("unroll")                                                      \
        for (int c_ = 0; c_ < 8; c_++) {                                       \
            float4 pa_ = pc_[2 * c_];                                          \
            float4 pb_ = pc_[2 * c_ + 1];                                      \
            ffma2(A_, (W)[c_].x, pa_.x, pa_.y);                                \
            ffma2(B_, (W)[c_].y, pa_.z, pa_.w);                                \
            ffma2(A_, (W)[c_].z, pb_.x, pb_.y);                                \
            ffma2(B_, (W)[c_].w, pb_.z, pb_.w);                                \
        }                                                                      \
        if (t + 2 < nsteps) LOADW(W, t + 2);                                   \
        float l0_, h0_, l1_, h1_;                                              \
        unpack2(A_, l0_, h0_);                                                 \
        unpack2(B_, l1_, h1_);                                                 \
        psm[(t + 1) & 1][j] = (l0_ + h0_) + (l1_ + h1_);                       \
        asm volatile("bar.sync %0, 64;" :: "r"(barid) : "memory");             \
        t++;                                                                   \
    }

__device__ __forceinline__ void run_dir(const uint4* __restrict__ pairs,
                                        const uint4* __restrict__ singles,
                                        const int* midx, int nsteps,
                                        float (*psm)[64], int j, int barid) {
    uint4 w0[8], w1[8];
    if (nsteps > 0) LOADW(w0, 0);
    if (nsteps > 1) LOADW(w1, 1);
    int t = 0;
    while (t < nsteps) {
        STEPD(w0);
        if (t >= nsteps) break;
        STEPD(w1);
    }
}

__global__ void __launch_bounds__(128, 1)
k_forward(const int* __restrict__ x, const int* __restrict__ lengths,
          const float* __restrict__ f_logits, float* __restrict__ out) {
    __shared__ __align__(16) float pL[2][QN];
    __shared__ __align__(16) float pR[2][QN];
    __shared__ int midxL[SN / 4 + 4];
    __shared__ int midxR[SN / 4 + 4];
    __shared__ float red[8];

    int b = blockIdx.x, tid = threadIdx.x;
    int L = __ldg(lengths + b);
    int np  = L >> 1;
    int npL = (np + 1) >> 1;
    int npR = np - npL;
    int odd = L & 1;
    int stepsR = npR + odd;
    int m = 2 * npL;
    const int* xb = x + b * SN;

    // left steps: pairs (x[2t], x[2t+1]) in order
    for (int t = tid; t < npL; t += 128)
        midxL[t] = (__ldg(xb + 2 * t) * 32 + __ldg(xb + 2 * t + 1)) * 4096;
    // right steps (processing order): odd tail single first, then pairs descending
    for (int s = tid; s < stepsR; s += 128) {
        int off;
        if (odd && s == 0) {
            off = __ldg(xb + L - 1) * 4096 | 1;
        } else {
            int k = npR - 1 - (s - odd);
            off = (__ldg(xb + m + 2 * k) * 32 + __ldg(xb + m + 2 * k + 1)) * 4096;
        }
        midxR[s] = off;
    }

    if (tid < 64) {
        pL[0][tid] = (tid == 0) ? 1.0f : 0.0f;
    } else {
        int j = tid - 64;
        float f = __ldg(f_logits + j);
        float Mv = f;
#pragma unroll
        for (int o = 16; o; o >>= 1) Mv = fmaxf(Mv, __shfl_xor_sync(0xFFFFFFFFu, Mv, o));
        if ((tid & 31) == 0) red[(tid >> 5) & 1] = Mv;
        asm volatile("bar.sync 2, 64;" ::: "memory");
        float M = fmaxf(red[0], red[1]);
        float e = expf(f - M);
        pR[0][j] = e;
        float S2 = e;
#pragma unroll
        for (int o = 16; o; o >>= 1) S2 += __shfl_xor_sync(0xFFFFFFFFu, S2, o);
        if ((tid & 31) == 0) red[2 + ((tid >> 5) & 1)] = S2;
    }
    __syncthreads();

    if (tid < 64)
        run_dir((const uint4*)g_pairs,  (const uint4*)g_singles,  midxL, npL,
                pL, tid, 1);
    else
        run_dir((const uint4*)g_pairsT, (const uint4*)g_singlesT, midxR, stepsR,
                pR, tid - 64, 2);
    __syncthreads();

    // out = log(alpha . r) - log(sum alpha) - log(sum e)
    if (tid < 64) {
        int wid = tid >> 5;
        float a = pL[npL & 1][tid];
        float r = pR[stepsR & 1][tid];
        float d = a * r, sa = a;
#pragma unroll
        for (int o = 16; o; o >>= 1) {
            d  += __shfl_xor_sync(0xFFFFFFFFu, d,  o);
            sa += __shfl_xor_sync(0xFFFFFFFFu, sa, o);
        }
        if ((tid & 31) == 0) { red[4 + wid] = d; red[6 + wid] = sa; }
    }
    __syncthreads();
    if (tid == 0)
        out[b] = logf(red[4] + red[5]) - logf(red[6] + red[7])
               - logf(red[2] + red[3]);
}

extern "C" void kernel_launch(void* const* d_in, const int* in_sizes, int n_in,
                              void* d_out, int out_size) {
    const int*   x        = (const int*)d_in[0];       // [256, 2048]
    const int*   lengths  = (const int*)d_in[1];       // [256]
    const float* T_logits = (const float*)d_in[2];     // [64, 32, 64]
    const float* f_logits = (const float*)d_in[3];     // [64]
    float* out = (float*)d_out;                        // [256]

    k_softmax<<<512, 128>>>(T_logits);
    k_pairs<<<1024, 64>>>();
    k_forward<<<BN, 128>>>(x, lengths, f_logits, out);
}

// round 4
// speedup vs baseline: 1.6798x; 1.2400x over previous
#include <cuda_runtime.h>
#include <cuda_bf16.h>

#define QN 64
#define AN 32
#define BN 256
#define SN 2048

// Interleaved bf16 layout for a 64x64 matrix W: element (i,j) at
//   bf16 index  (i>>3)*512 + j*8 + (i&7)
// One 16B granule = rows 8c..8c+7 of column j. Column-j access = 8 x uint4,
// perfectly coalesced across a warp.
__device__ __align__(16) static __nv_bfloat16 g_pairs  [1024 * 4096];  // P[a0*32+a1]
__device__ __align__(16) static __nv_bfloat16 g_pairsT [1024 * 4096];  // P^T
__device__ __align__(16) static __nv_bfloat16 g_singles [32 * 4096];   // W[a]
__device__ __align__(16) static __nv_bfloat16 g_singlesT[32 * 4096];   // W[a]^T
__device__ __align__(16) static float g_Wf[32 * 4096];                 // f32 W[a]
__device__ static int   g_next;                                        // work counter
__device__ static short g_order[BN];                                   // seq ids, desc length

// ---------------------------------------------------------------------------
// Kernel 1: W[a][i][j] = softmax_j(T_logits[i][a][:]). One warp per (i,a).
// ---------------------------------------------------------------------------
__global__ void k_softmax(const float* __restrict__ T) {
    int warp = (blockIdx.x << 2) + (threadIdx.x >> 5);   // warp = i*32 + a
    int lane = threadIdx.x & 31;
    int i = warp >> 5, a = warp & 31;
    const float* row = T + warp * 64;
    float v0 = row[lane], v1 = row[lane + 32];
    float m = fmaxf(v0, v1);
#pragma unroll
    for (int o = 16; o; o >>= 1) m = fmaxf(m, __shfl_xor_sync(0xFFFFFFFFu, m, o));
    float e0 = expf(v0 - m), e1 = expf(v1 - m);
    float s = e0 + e1;
#pragma unroll
    for (int o = 16; o; o >>= 1) s += __shfl_xor_sync(0xFFFFFFFFu, s, o);
    float inv = 1.0f / s;
    float w0 = e0 * inv, w1 = e1 * inv;

    float* wf = g_Wf + a * 4096 + i * 64;
    wf[lane] = w0;
    wf[lane + 32] = w1;

    __nv_bfloat16* sg  = g_singles  + a * 4096;
    __nv_bfloat16* sgT = g_singlesT + a * 4096;
    int c = i >> 3, r = i & 7;
    int j0 = lane, j1 = lane + 32;
    sg[c * 512 + j0 * 8 + r] = __float2bfloat16(w0);
    sg[c * 512 + j1 * 8 + r] = __float2bfloat16(w1);
    sgT[(j0 >> 3) * 512 + i * 8 + (j0 & 7)] = __float2bfloat16(w0);
    sgT[(j1 >> 3) * 512 + i * 8 + (j1 & 7)] = __float2bfloat16(w1);
}

// ---------------------------------------------------------------------------
// Kernel 1b: rank-sort sequence ids by length descending; reset work counter.
// ---------------------------------------------------------------------------
__global__ void k_sort(const int* __restrict__ lengths) {
    __shared__ int Ls[BN];
    int t = threadIdx.x;
    int L = lengths[t];
    Ls[t] = L;
    __syncthreads();
    int rank = 0;
#pragma unroll 8
    for (int i = 0; i < BN; i++) {
        int Li = Ls[i];
        rank += (Li > L) || (Li == L && i < t);
    }
    g_order[rank] = (short)t;
    if (t == 0) g_next = 0;
}

// ---------------------------------------------------------------------------
// Kernel 2: P = W[a0] @ W[a1], f32 math; bf16 interleaved P and P^T outputs.
// ---------------------------------------------------------------------------
__global__ void k_pairs() {
    __shared__ __align__(16) float As[64][68];   // As[k][i] = A[i][k]
    __shared__ __align__(16) float Bs[64][64];   // Bs[k][j] = B[k][j]
    int a0 = blockIdx.x >> 5, a1 = blockIdx.x & 31;
    const float* A  = g_Wf + a0 * 4096;
    const float* Bm = g_Wf + a1 * 4096;
    int t = threadIdx.x;
    for (int idx = t; idx < 4096; idx += 64) {
        As[idx & 63][idx >> 6] = A[idx];
        Bs[idx >> 6][idx & 63] = Bm[idx];
    }
    __syncthreads();

    int j0 = (t & 7) << 3, i0 = (t >> 3) << 3;
    float acc[8][8];
#pragma unroll
    for (int ii = 0; ii < 8; ii++)
#pragma unroll
        for (int jj = 0; jj < 8; jj++) acc[ii][jj] = 0.f;

    for (int k = 0; k < 64; k++) {
        float av[8], bv[8];
        *(float4*)(av)     = *(const float4*)&As[k][i0];
        *(float4*)(av + 4) = *(const float4*)&As[k][i0 + 4];
        *(float4*)(bv)     = *(const float4*)&Bs[k][j0];
        *(float4*)(bv + 4) = *(const float4*)&Bs[k][j0 + 4];
#pragma unroll
        for (int ii = 0; ii < 8; ii++)
#pragma unroll
            for (int jj = 0; jj < 8; jj++)
                acc[ii][jj] = fmaf(av[ii], bv[jj], acc[ii][jj]);
    }

    __nv_bfloat16* dst = g_pairs + blockIdx.x * 4096 + (i0 >> 3) * 512;
#pragma unroll
    for (int jj = 0; jj < 8; jj++) {
        __nv_bfloat162 h0 = __floats2bfloat162_rn(acc[0][jj], acc[1][jj]);
        __nv_bfloat162 h1 = __floats2bfloat162_rn(acc[2][jj], acc[3][jj]);
        __nv_bfloat162 h2 = __floats2bfloat162_rn(acc[4][jj], acc[5][jj]);
        __nv_bfloat162 h3 = __floats2bfloat162_rn(acc[6][jj], acc[7][jj]);
        uint4 u;
        u.x = *(unsigned*)&h0; u.y = *(unsigned*)&h1;
        u.z = *(unsigned*)&h2; u.w = *(unsigned*)&h3;
        *(uint4*)(dst + (j0 + jj) * 8) = u;
    }
    __nv_bfloat16* dstT = g_pairsT + blockIdx.x * 4096 + (j0 >> 3) * 512;
#pragma unroll
    for (int ii = 0; ii < 8; ii++) {
        __nv_bfloat162 h0 = __floats2bfloat162_rn(acc[ii][0], acc[ii][1]);
        __nv_bfloat162 h1 = __floats2bfloat162_rn(acc[ii][2], acc[ii][3]);
        __nv_bfloat162 h2 = __floats2bfloat162_rn(acc[ii][4], acc[ii][5]);
        __nv_bfloat162 h3 = __floats2bfloat162_rn(acc[ii][6], acc[ii][7]);
        uint4 u;
        u.x = *(unsigned*)&h0; u.y = *(unsigned*)&h1;
        u.z = *(unsigned*)&h2; u.w = *(unsigned*)&h3;
        *(uint4*)(dstT + (i0 + ii) * 8) = u;
    }
}

// ---------------------------------------------------------------------------
// Kernel 3: persistent bidirectional forward. 148 CTAs x 128 threads; each CTA
// grabs sequences (longest-first) from a global atomic queue.
// warps 0-1: left  alpha <- alpha * P ; warps 2-3: right r <- P^T-form * r.
// ---------------------------------------------------------------------------
__device__ __forceinline__ void ffma2(unsigned long long& acc, unsigned u,
                                      float pl, float ph) {
    asm("{\n\t"
        ".reg .b32 wl, wh;\n\t"
        ".reg .b64 w2, p2;\n\t"
        "shl.b32 wl, %1, 16;\n\t"
        "and.b32 wh, %1, 0xFFFF0000;\n\t"
        "mov.b64 w2, {wl, wh};\n\t"
        "mov.b64 p2, {%2, %3};\n\t"
        "fma.rn.f32x2 %0, w2, p2, %0;\n\t"
        "}" : "+l"(acc) : "r"(u), "f"(pl), "f"(ph));
}
__device__ __forceinline__ void unpack2(unsigned long long a, float& lo, float& hi) {
    asm("mov.b64 {%0, %1}, %2;" : "=f"(lo), "=f"(hi) : "l"(a));
}

#define LOADW(W, T_)                                                           \
    {                                                                          \
        int off_ = midx[(T_)];                                                 \
        const uint4* base_ =                                                   \
            ((off_ & 1) ? singles : pairs) + ((off_ & ~1) >> 3) + j;           \
        _Pragma("unroll")                                                      \
        for (int c_ = 0; c_ < 8; c_++) (W)[c_] = __ldg(base_ + c_ * 64);       \
    }

#define STEPD(W)                                                               \
    {                                                                          \
        const float4* pc_ = (const float4*)psm[t & 1];                         \
        unsigned long long A_ = 0ull, B_ = 0ull, C_ = 0ull, D_ = 0ull;         \
        _Pragma("unroll")                                                      \
        for (int c_ = 0; c_ < 8; c_++) {                                       \
            float4 pa_ = pc_[2 * c_];                                          \
            float4 pb_ = pc_[2 * c_ + 1];                                      \
            ffma2(A_, (W)[c_].x, pa_.x, pa_.y);                                \
            ffma2(B_, (W)[c_].y, pa_.z, pa_.w);                                \
            ffma2(C_, (W)[c_].z, pb_.x, pb_.y);                                \
            ffma2(D_, (W)[c_].w, pb_.z, pb_.w);                                \
        }                                                                      \
        if (t + 2 < nsteps) LOADW(W, t + 2);                                   \
        float l0_, h0_, l1_, h1_, l2_, h2_, l3_, h3_;                          \
        unpack2(A_, l0_, h0_);                                                 \
        unpack2(B_, l1_, h1_);                                                 \
        unpack2(C_, l2_, h2_);                                                 \
        unpack2(D_, l3_, h3_);                                                 \
        psm[(t + 1) & 1][j] = ((l0_ + h0_) + (l1_ + h1_))                      \
                            + ((l2_ + h2_) + (l3_ + h3_));                     \
        asm volatile("bar.sync %0, 64;" :: "r"(barid) : "memory");             \
        t++;                                                                   \
    }

__device__ __forceinline__ void run_dir(const uint4* __restrict__ pairs,
                                        const uint4* __restrict__ singles,
                                        const int* midx, int nsteps,
                                        float (*psm)[64], int j, int barid) {
    uint4 w0[8], w1[8];
    if (nsteps > 0) LOADW(w0, 0);
    if (nsteps > 1) LOADW(w1, 1);
    int t = 0;
    while (t < nsteps) {
        STEPD(w0);
        if (t >= nsteps) break;
        STEPD(w1);
    }
}

__global__ void __launch_bounds__(128, 1)
k_forward(const int* __restrict__ x, const int* __restrict__ lengths,
          const float* __restrict__ f_logits, float* __restrict__ out) {
    __shared__ __align__(16) float pL[2][QN];
    __shared__ __align__(16) float pR[2][QN];
    __shared__ __align__(16) float ef[QN];      // exp(f - M), hoisted
    __shared__ int midxL[SN / 4 + 4];
    __shared__ int midxR[SN / 4 + 4];
    __shared__ float red[8];
    __shared__ float sLogS2;
    __shared__ int s_grab;

    int tid = threadIdx.x;

    // ---- hoisted f_logits prep (constant across sequences) ----
    if (tid < 64) {
        float f = __ldg(f_logits + tid);
        float Mv = f;
#pragma unroll
        for (int o = 16; o; o >>= 1) Mv = fmaxf(Mv, __shfl_xor_sync(0xFFFFFFFFu, Mv, o));
        if ((tid & 31) == 0) red[tid >> 5] = Mv;
        asm volatile("bar.sync 1, 64;" ::: "memory");
        float M = fmaxf(red[0], red[1]);
        float e = expf(f - M);
        ef[tid] = e;
        float S2 = e;
#pragma unroll
        for (int o = 16; o; o >>= 1) S2 += __shfl_xor_sync(0xFFFFFFFFu, S2, o);
        if ((tid & 31) == 0) red[2 + (tid >> 5)] = S2;
        asm volatile("bar.sync 1, 64;" ::: "memory");
        if (tid == 0) sLogS2 = logf(red[2] + red[3]);
    }
    __syncthreads();

    // ---- persistent work loop ----
    while (true) {
        if (tid == 0) s_grab = atomicAdd(&g_next, 1);
        __syncthreads();
        int s = s_grab;
        if (s >= BN) return;
        int b = g_order[s];

        int L = __ldg(lengths + b);
        int np  = L >> 1;
        int npL = (np + 1) >> 1;
        int npR = np - npL;
        int odd = L & 1;
        int stepsR = npR + odd;
        int m = 2 * npL;
        const int* xb = x + b * SN;

        for (int t = tid; t < npL; t += 128)
            midxL[t] = (__ldg(xb + 2 * t) * 32 + __ldg(xb + 2 * t + 1)) * 4096;
        for (int s2 = tid; s2 < stepsR; s2 += 128) {
            int off;
            if (odd && s2 == 0) {
                off = __ldg(xb + L - 1) * 4096 | 1;
            } else {
                int k = npR - 1 - (s2 - odd);
                off = (__ldg(xb + m + 2 * k) * 32 + __ldg(xb + m + 2 * k + 1)) * 4096;
            }
            midxR[s2] = off;
        }
        if (tid < 64) pL[0][tid] = (tid == 0) ? 1.0f : 0.0f;
        else          pR[0][tid - 64] = ef[tid - 64];
        __syncthreads();

        if (tid < 64)
            run_dir((const uint4*)g_pairs,  (const uint4*)g_singles,  midxL, npL,
                    pL, tid, 1);
        else
            run_dir((const uint4*)g_pairsT, (const uint4*)g_singlesT, midxR, stepsR,
                    pR, tid - 64, 2);
        __syncthreads();

        if (tid < 64) {
            int wid = tid >> 5;
            float a = pL[npL & 1][tid];
            float r = pR[stepsR & 1][tid];
            float d = a * r, sa = a;
#pragma unroll
            for (int o = 16; o; o >>= 1) {
                d  += __shfl_xor_sync(0xFFFFFFFFu, d,  o);
                sa += __shfl_xor_sync(0xFFFFFFFFu, sa, o);
            }
            if ((tid & 31) == 0) { red[4 + wid] = d; red[6 + wid] = sa; }
        }
        __syncthreads();
        if (tid == 0)
            out[b] = logf(red[4] + red[5]) - logf(red[6] + red[7]) - sLogS2;
        __syncthreads();
    }
}

extern "C" void kernel_launch(void* const* d_in, const int* in_sizes, int n_in,
                              void* d_out, int out_size) {
    const int*   x        = (const int*)d_in[0];       // [256, 2048]
    const int*   lengths  = (const int*)d_in[1];       // [256]
    const float* T_logits = (const float*)d_in[2];     // [64, 32, 64]
    const float* f_logits = (const float*)d_in[3];     // [64]
    float* out = (float*)d_out;                        // [256]

    k_softmax<<<512, 128>>>(T_logits);
    k_sort<<<1, BN>>>(lengths);
    k_pairs<<<1024, 64>>>();
    k_forward<<<148, 128>>>(x, lengths, f_logits, out);
}

// round 5
// speedup vs baseline: 1.7998x; 1.0714x over previous
#include <cuda_runtime.h>
#include <cuda_bf16.h>

#define QN 64
#define AN 32
#define BN 256
#define SN 2048

// Interleaved bf16 layout for a 64x64 matrix W: element (i,j) at
//   bf16 index  (i>>3)*512 + j*8 + (i&7)
// One 16B granule = rows 8c..8c+7 of column j.
__device__ __align__(16) static __nv_bfloat16 g_pairs  [1024 * 4096];  // P[a0*32+a1]
__device__ __align__(16) static __nv_bfloat16 g_pairsT [1024 * 4096];  // P^T
__device__ __align__(16) static __nv_bfloat16 g_singles [32 * 4096];   // W[a]
__device__ __align__(16) static __nv_bfloat16 g_singlesT[32 * 4096];   // W[a]^T
__device__ __align__(16) static float g_Wf[32 * 4096];                 // f32 W[a]
__device__ static int   g_next;                                        // work counter
__device__ static short g_order[BN];                                   // ids, desc length

// ---------------------------------------------------------------------------
// Kernel 1: W[a][i][j] = softmax_j(T_logits[i][a][:]). One warp per (i,a).
// ---------------------------------------------------------------------------
__global__ void k_softmax(const float* __restrict__ T) {
    int warp = (blockIdx.x << 2) + (threadIdx.x >> 5);   // warp = i*32 + a
    int lane = threadIdx.x & 31;
    int i = warp >> 5, a = warp & 31;
    const float* row = T + warp * 64;
    float v0 = row[lane], v1 = row[lane + 32];
    float m = fmaxf(v0, v1);
#pragma unroll
    for (int o = 16; o; o >>= 1) m = fmaxf(m, __shfl_xor_sync(0xFFFFFFFFu, m, o));
    float e0 = expf(v0 - m), e1 = expf(v1 - m);
    float s = e0 + e1;
#pragma unroll
    for (int o = 16; o; o >>= 1) s += __shfl_xor_sync(0xFFFFFFFFu, s, o);
    float inv = 1.0f / s;
    float w0 = e0 * inv, w1 = e1 * inv;

    float* wf = g_Wf + a * 4096 + i * 64;
    wf[lane] = w0;
    wf[lane + 32] = w1;

    __nv_bfloat16* sg  = g_singles  + a * 4096;
    __nv_bfloat16* sgT = g_singlesT + a * 4096;
    int c = i >> 3, r = i & 7;
    int j0 = lane, j1 = lane + 32;
    sg[c * 512 + j0 * 8 + r] = __float2bfloat16(w0);
    sg[c * 512 + j1 * 8 + r] = __float2bfloat16(w1);
    sgT[(j0 >> 3) * 512 + i * 8 + (j0 & 7)] = __float2bfloat16(w0);
    sgT[(j1 >> 3) * 512 + i * 8 + (j1 & 7)] = __float2bfloat16(w1);
}

// ---------------------------------------------------------------------------
// Kernel 1b: rank-sort sequence ids by length descending; reset work counter.
// ---------------------------------------------------------------------------
__global__ void k_sort(const int* __restrict__ lengths) {
    __shared__ int Ls[BN];
    int t = threadIdx.x;
    int L = lengths[t];
    Ls[t] = L;
    __syncthreads();
    int rank = 0;
#pragma unroll 8
    for (int i = 0; i < BN; i++) {
        int Li = Ls[i];
        rank += (Li > L) || (Li == L && i < t);
    }
    g_order[rank] = (short)t;
    if (t == 0) g_next = 0;
}

// ---------------------------------------------------------------------------
// Kernel 2: P = W[a0]@W[a1]; writes bf16 interleaved P AND P^T.
// 1024 CTAs x 128 threads (all 4 SMSPs), 8x4 register tiles, smem round-trip
// for the transposed emission.
// ---------------------------------------------------------------------------
__device__ __forceinline__ unsigned packbf(float a, float b) {
    __nv_bfloat162 h = __floats2bfloat162_rn(a, b);
    return *(unsigned*)&h;
}

__global__ void k_pairs() {
    __shared__ __align__(16) float As[64][68];   // As[k][i] = A[i][k]; reused as OutS[i][j]
    __shared__ __align__(16) float Bs[64][64];   // Bs[k][j] = B[k][j]
    int mId = blockIdx.x;
    int a0 = mId >> 5, a1 = mId & 31;
    const float* A  = g_Wf + a0 * 4096;
    const float* Bm = g_Wf + a1 * 4096;
    int t = threadIdx.x;
    for (int idx = t; idx < 4096; idx += 128) {
        As[idx & 63][idx >> 6] = A[idx];
        Bs[idx >> 6][idx & 63] = Bm[idx];
    }
    __syncthreads();

    int i0 = (t >> 4) << 3, j0 = (t & 15) << 2;   // 8 rows x 4 cols per thread
    float acc[8][4];
#pragma unroll
    for (int r = 0; r < 8; r++)
#pragma unroll
        for (int c = 0; c < 4; c++) acc[r][c] = 0.f;

    for (int k = 0; k < 64; k++) {
        float av[8];
        *(float4*)(av)     = *(const float4*)&As[k][i0];
        *(float4*)(av + 4) = *(const float4*)&As[k][i0 + 4];
        float4 bv = *(const float4*)&Bs[k][j0];
#pragma unroll
        for (int r = 0; r < 8; r++) {
            acc[r][0] = fmaf(av[r], bv.x, acc[r][0]);
            acc[r][1] = fmaf(av[r], bv.y, acc[r][1]);
            acc[r][2] = fmaf(av[r], bv.z, acc[r][2]);
            acc[r][3] = fmaf(av[r], bv.w, acc[r][3]);
        }
    }
    __syncthreads();
    // stage result into As as OutS[i][j] (row stride 68)
#pragma unroll
    for (int r = 0; r < 8; r++)
#pragma unroll
        for (int c = 0; c < 4; c++) As[i0 + r][j0 + c] = acc[r][c];
    __syncthreads();

    __nv_bfloat16* dstN = g_pairs  + mId * 4096;
    __nv_bfloat16* dstT = g_pairsT + mId * 4096;
#pragma unroll
    for (int q = 0; q < 4; q++) {
        int g = t + 128 * q;              // granule id 0..511
        int c = g >> 6, j = g & 63;
        uint4 u;
        u.x = packbf(As[8 * c + 0][j], As[8 * c + 1][j]);
        u.y = packbf(As[8 * c + 2][j], As[8 * c + 3][j]);
        u.z = packbf(As[8 * c + 4][j], As[8 * c + 5][j]);
        u.w = packbf(As[8 * c + 6][j], As[8 * c + 7][j]);
        *(uint4*)(dstN + c * 512 + j * 8) = u;
        // transposed granule: rows of P^T = cols of P
        int i = g & 63, cT = g >> 6;
        const float* rp = &As[i][8 * cT];
        uint4 v;
        v.x = packbf(rp[0], rp[1]);
        v.y = packbf(rp[2], rp[3]);
        v.z = packbf(rp[4], rp[5]);
        v.w = packbf(rp[6], rp[7]);
        *(uint4*)(dstT + cT * 512 + i * 8) = v;
    }
}

// ---------------------------------------------------------------------------
// Kernel 3: persistent bidirectional forward. 148 CTAs x 256 threads.
// warps 0-3: left (alpha <- alpha P), warps 4-7: right (r <- P r via P^T).
// Each column j handled by a LANE PAIR (l, l+16) of one warp: lane l does
// k-chunks 0-3, lane l+16 does k-chunks 4-7; combine via shfl_down(16).
// ---------------------------------------------------------------------------
__device__ __forceinline__ void ffma2(unsigned long long& acc, unsigned u,
                                      unsigned long long p2) {
    asm("{\n\t"
        ".reg .b32 wl, wh;\n\t"
        ".reg .b64 w2;\n\t"
        "shl.b32 wl, %1, 16;\n\t"
        "and.b32 wh, %1, 0xFFFF0000;\n\t"
        "mov.b64 w2, {wl, wh};\n\t"
        "fma.rn.f32x2 %0, w2, %2, %0;\n\t"
        "}" : "+l"(acc) : "r"(u), "l"(p2));
}
__device__ __forceinline__ unsigned long long addx2(unsigned long long a,
                                                    unsigned long long b) {
    unsigned long long r;
    asm("add.rn.f32x2 %0, %1, %2;" : "=l"(r) : "l"(a), "l"(b));
    return r;
}
__device__ __forceinline__ void unpack2(unsigned long long a, float& lo, float& hi) {
    asm("mov.b64 {%0, %1}, %2;" : "=f"(lo), "=f"(hi) : "l"(a));
}

#define LOADW(W, T_)                                                           \
    {                                                                          \
        int off_ = midx[(T_)];                                                 \
        const uint4* b_ =                                                      \
            ((off_ & 1) ? singles : pairs) + ((off_ & ~1) >> 3) + goff;        \
        _Pragma("unroll")                                                      \
        for (int q_ = 0; q_ < 4; q_++) (W)[q_] = __ldg(b_ + q_ * 64);          \
    }

#define STEPD(W)                                                               \
    {                                                                          \
        const ulonglong2* pc_ = (const ulonglong2*)(psm[t & 1] + cbase * 8);   \
        unsigned long long A_ = 0ull, B_ = 0ull, C_ = 0ull, D_ = 0ull;         \
        _Pragma("unroll")                                                      \
        for (int q_ = 0; q_ < 4; q_++) {                                       \
            ulonglong2 d0_ = pc_[2 * q_];                                      \
            ulonglong2 d1_ = pc_[2 * q_ + 1];                                  \
            uint4 u_ = (W)[q_];                                                \
            ffma2(A_, u_.x, d0_.x);                                            \
            ffma2(B_, u_.y, d0_.y);                                            \
            ffma2(C_, u_.z, d1_.x);                                            \
            ffma2(D_, u_.w, d1_.y);                                            \
        }                                                                      \
        if (t + 2 < nsteps) LOADW(W, t + 2);                                   \
        A_ = addx2(A_, B_);                                                    \
        C_ = addx2(C_, D_);                                                    \
        A_ = addx2(A_, C_);                                                    \
        float lo_, hi_;                                                        \
        unpack2(A_, lo_, hi_);                                                 \
        float v_ = lo_ + hi_;                                                  \
        v_ += __shfl_down_sync(0xFFFFFFFFu, v_, 16);                           \
        if (lane < 16) psm[(t + 1) & 1][j] = v_;                               \
        asm volatile("bar.sync %0, 128;" :: "r"(barid) : "memory");            \
        t++;                                                                   \
    }

__device__ __forceinline__ void run_dir(const uint4* __restrict__ pairs,
                                        const uint4* __restrict__ singles,
                                        const int* midx, int nsteps,
                                        float (*psm)[QN], int t128, int barid) {
    int lane = t128 & 31;
    int j = ((t128 >> 5) << 4) | (lane & 15);   // warp*16 + lane%16
    int cbase = (lane >> 4) << 2;               // 0 or 4
    int goff = cbase * 64 + j;                  // granule offset (chunk cbase, col j)
    uint4 w0[4], w1[4];
    if (nsteps > 0) LOADW(w0, 0);
    if (nsteps > 1) LOADW(w1, 1);
    int t = 0;
    while (t < nsteps) {
        STEPD(w0);
        if (t >= nsteps) break;
        STEPD(w1);
    }
}

__global__ void __launch_bounds__(256, 1)
k_forward(const int* __restrict__ x, const int* __restrict__ lengths,
          const float* __restrict__ f_logits, float* __restrict__ out) {
    __shared__ __align__(16) float pL[2][QN];
    __shared__ __align__(16) float pR[2][QN];
    __shared__ __align__(16) float ef[QN];      // exp(f - M), hoisted
    __shared__ int midxL[SN / 4 + 4];
    __shared__ int midxR[SN / 4 + 4];
    __shared__ float red[8];
    __shared__ float sLogS2;
    __shared__ int s_grab;

    int tid = threadIdx.x;

    // ---- hoisted f_logits prep (constant across sequences) ----
    if (tid < 64) {
        float f = __ldg(f_logits + tid);
        float Mv = f;
#pragma unroll
        for (int o = 16; o; o >>= 1) Mv = fmaxf(Mv, __shfl_xor_sync(0xFFFFFFFFu, Mv, o));
        if ((tid & 31) == 0) red[tid >> 5] = Mv;
        asm volatile("bar.sync 7, 64;" ::: "memory");
        float M = fmaxf(red[0], red[1]);
        float e = expf(f - M);
        ef[tid] = e;
        float S2 = e;
#pragma unroll
        for (int o = 16; o; o >>= 1) S2 += __shfl_xor_sync(0xFFFFFFFFu, S2, o);
        if ((tid & 31) == 0) red[2 + (tid >> 5)] = S2;
        asm volatile("bar.sync 7, 64;" ::: "memory");
        if (tid == 0) sLogS2 = logf(red[2] + red[3]);
    }
    __syncthreads();

    // ---- persistent work loop (longest-first via g_order) ----
    while (true) {
        if (tid == 0) s_grab = atomicAdd(&g_next, 1);
        __syncthreads();
        int s = s_grab;
        if (s >= BN) return;
        int b = g_order[s];

        int L = __ldg(lengths + b);
        int np  = L >> 1;
        int npL = (np + 1) >> 1;
        int npR = np - npL;
        int odd = L & 1;
        int stepsR = npR + odd;
        int m = 2 * npL;
        const int* xb = x + b * SN;

        for (int t = tid; t < npL; t += 256)
            midxL[t] = (__ldg(xb + 2 * t) * 32 + __ldg(xb + 2 * t + 1)) * 4096;
        for (int s2 = tid; s2 < stepsR; s2 += 256) {
            int off;
            if (odd && s2 == 0) {
                off = __ldg(xb + L - 1) * 4096 | 1;
            } else {
                int k = npR - 1 - (s2 - odd);
                off = (__ldg(xb + m + 2 * k) * 32 + __ldg(xb + m + 2 * k + 1)) * 4096;
            }
            midxR[s2] = off;
        }
        if (tid < 64)       pL[0][tid] = (tid == 0) ? 1.0f : 0.0f;
        else if (tid < 128) pR[0][tid - 64] = ef[tid - 64];
        __syncthreads();

        if (tid < 128)
            run_dir((const uint4*)g_pairs,  (const uint4*)g_singles,  midxL, npL,
                    pL, tid, 1);
        else
            run_dir((const uint4*)g_pairsT, (const uint4*)g_singlesT, midxR, stepsR,
                    pR, tid - 128, 2);
        __syncthreads();

        if (tid < 64) {
            int wid = tid >> 5;
            float a = pL[npL & 1][tid];
            float r = pR[stepsR & 1][tid];
            float d = a * r, sa = a;
#pragma unroll
            for (int o = 16; o; o >>= 1) {
                d  += __shfl_xor_sync(0xFFFFFFFFu, d,  o);
                sa += __shfl_xor_sync(0xFFFFFFFFu, sa, o);
            }
            if ((tid & 31) == 0) { red[4 + wid] = d; red[6 + wid] = sa; }
        }
        __syncthreads();
        if (tid == 0)
            out[b] = logf(red[4] + red[5]) - logf(red[6] + red[7]) - sLogS2;
        __syncthreads();
    }
}

extern "C" void kernel_launch(void* const* d_in, const int* in_sizes, int n_in,
                              void* d_out, int out_size) {
    const int*   x        = (const int*)d_in[0];       // [256, 2048]
    const int*   lengths  = (const int*)d_in[1];       // [256]
    const float* T_logits = (const float*)d_in[2];     // [64, 32, 64]
    const float* f_logits = (const float*)d_in[3];     // [64]
    float* out = (float*)d_out;                        // [256]

    k_softmax<<<512, 128>>>(T_logits);
    k_sort<<<1, BN>>>(lengths);
    k_pairs<<<1024, 128>>>();
    k_forward<<<148, 256>>>(x, lengths, f_logits, out);
}